// round 7
// baseline (speedup 1.0000x reference)
#include <cuda_runtime.h>
#include <cuda_fp16.h>
#include <cstdint>

#define DINLINE __device__ __forceinline__

static constexpr int Bd = 2048;
static constexpr int Hd = 256;
static constexpr int Td = 512;
static constexpr int MT = 128;                 // batch tile rows
static constexpr int NT = 128;                 // gate-column tile
static constexpr int NGRP = Bd / MT;           // 16 M-groups (= clusters)
static constexpr int NSLC = (4 * Hd) / NT;     // 8 N-slices (= cluster size)
static constexpr int GRID = NGRP * NSLC;       // 128 CTAs
static constexpr int NTHR = 512;               // 16 warps: 4 (M) x 4 (N), 32x32 warp tiles

// SMEM layout (dynamic)
static constexpr int SM_BIAS = 0;              // 128 floats (float4 per hidden unit: i,f,g,o)
static constexpr int SM_MBAR = 512;            // two mbarriers (ping-pong by step parity)
static constexpr int SM_A = 1024;              // h tile [128][256] f16, XOR-swizzled (64KB)
static constexpr int SM_W = SM_A + 65536;      // W tile [128 n][256 k] f16, XOR-swizzled (64KB)
static constexpr int SM_TOTAL = SM_W + 65536;  // 132096 B

// ---------------- device globals (scratch; no allocations) ----------------
__device__ __align__(16) __half g_hbuf[2][Bd * Hd];                  // ping-pong h (fp16)
__device__ __align__(1024) unsigned char g_Wimg[2][NSLC][65536];     // [W_ih, W_ih+W_hh] smem images
__device__ float g_bias[NSLC][NT];

// ---------------- helpers ----------------
DINLINE uint32_t smem_u32(const void* p) {
    uint32_t a;
    asm("{ .reg .u64 t; cvta.to.shared.u64 t, %1; cvt.u32.u64 %0, t; }" : "=r"(a) : "l"(p));
    return a;
}
DINLINE void cp16(uint32_t s, const void* g) {
    asm volatile("cp.async.cg.shared.global [%0], [%1], 16;" :: "r"(s), "l"(g));
}
DINLINE void cp_commit() { asm volatile("cp.async.commit_group;" ::: "memory"); }
DINLINE void cp_wait0()  { asm volatile("cp.async.wait_group 0;" ::: "memory"); }
DINLINE void cp_wait1()  { asm volatile("cp.async.wait_group 1;" ::: "memory"); }

DINLINE void ldsm4(uint32_t* r, uint32_t addr) {
    asm volatile("ldmatrix.sync.aligned.m8n8.x4.shared.b16 {%0,%1,%2,%3}, [%4];"
                 : "=r"(r[0]), "=r"(r[1]), "=r"(r[2]), "=r"(r[3]) : "r"(addr));
}
DINLINE void mma16816(float* c, const uint32_t* a, uint32_t b0, uint32_t b1) {
    asm volatile(
        "mma.sync.aligned.m16n8k16.row.col.f32.f16.f16.f32 "
        "{%0,%1,%2,%3},{%4,%5,%6,%7},{%8,%9},{%0,%1,%2,%3};"
        : "+f"(c[0]), "+f"(c[1]), "+f"(c[2]), "+f"(c[3])
        : "r"(a[0]), "r"(a[1]), "r"(a[2]), "r"(a[3]), "r"(b0), "r"(b1));
}

// sigmoid via single-MUFU tanh.approx; tanh (feeds h directly) stays EX2+RCP precise
DINLINE float fsig(float x) {
    float t;
    asm("tanh.approx.f32 %0, %1;" : "=f"(t) : "f"(0.5f * x));
    return fmaf(0.5f, t, 0.5f);
}
DINLINE float ftanh(float x) {
    float e, r;
    asm("ex2.approx.f32 %0, %1;" : "=f"(e) : "f"(2.8853900817779268f * x));
    asm("rcp.approx.f32 %0, %1;" : "=f"(r) : "f"(1.0f + e));
    return fmaf(-2.0f, r, 1.0f);
}

DINLINE uint32_t cluster_rank() {
    uint32_t r;
    asm("mov.u32 %0, %%cluster_ctarank;" : "=r"(r));
    return r;
}
DINLINE void mbar_arrive_remote(uint32_t local_mbar, uint32_t peer) {
    uint32_t remote;
    asm("mapa.shared::cluster.u32 %0, %1, %2;" : "=r"(remote) : "r"(local_mbar), "r"(peer));
    asm volatile("mbarrier.arrive.release.cluster.shared::cluster.b64 _, [%0];"
                 :: "r"(remote) : "memory");
}
DINLINE void mbar_wait_cl(uint32_t mbar, uint32_t parity) {
    asm volatile(
        "{\n\t.reg .pred P1;\n"
        "WL_%=:\n\tmbarrier.try_wait.parity.acquire.cluster.shared::cta.b64 P1, [%0], %1, 0x989680;\n"
        "\t@P1 bra WD_%=;\n\tbra WL_%=;\nWD_%=:\n\t}"
        :: "r"(mbar), "r"(parity) : "memory");
}
DINLINE void cluster_sync() {
    asm volatile("barrier.cluster.arrive.aligned;" ::: "memory");
    asm volatile("barrier.cluster.wait.aligned;" ::: "memory");
}

// ---------------- prologue: permuted/swizzled fp16 W images, bias, x->fp16 ----------------
// Column permutation within a 128-col slice: 16-col groups; w=n&15:
//   w<8:  gates (i,f)  unit = 4*(n>>4) + (w>>1), gate = w&1
//   w>=8: gates (g,o)  unit = 4*(n>>4) + ((w-8)>>1), gate = 2 + (w&1)
// -> MMA thread owning cols {2c,2c+1} of n8-tiles (2p, 2p+1) gets all 4 gates of one unit.
__global__ void prep_kernel(const float* __restrict__ x,
                            const float* __restrict__ Wih, const float* __restrict__ Whh,
                            const float* __restrict__ bih, const float* __restrict__ bhh) {
    int g = blockIdx.x * blockDim.x + threadIdx.x;
    if (g < Bd * Hd) g_hbuf[0][g] = __float2half_rn(x[g]);
    if (g < 2 * NSLC * NT * Hd) {  // 524288 entries
        int set = g >> 18;
        int r = g & 262143;
        int j = r >> 15;
        int n = (r >> 8) & 127;
        int k = r & 255;
        int w = n & 15;
        int gate = 2 * (w >> 3) + (w & 1);
        int hl = (n >> 4) * 4 + ((w >> 1) & 3);
        int row = gate * Hd + j * 32 + hl;            // original W row in (4H,H)
        float wv = Wih[row * Hd + k];
        if (set) wv += Whh[row * Hd + k];
        uint32_t byte = (uint32_t)(n * 512 + (((k >> 3) ^ (n & 7)) << 4) + (k & 7) * 2);
        *reinterpret_cast<__half*>(&g_Wimg[set][j][byte]) = __float2half_rn(wv);
    }
    if (g < NSLC * NT) {           // bias as float4 (i,f,g,o) per unit: n = unit*4+gate
        int j = g >> 7, n = g & 127;
        int gate = n & 3, hl = n >> 2;
        int row = gate * Hd + j * 32 + hl;
        g_bias[j][n] = bih[row] + bhh[row];
    }
}

// ---------------- main persistent kernel ----------------
__global__ void __launch_bounds__(NTHR, 1) __cluster_dims__(NSLC, 1, 1)
lstm_kernel(float* __restrict__ out) {
    extern __shared__ __align__(1024) char smem[];
    const uint32_t sb = smem_u32(smem);
    const int tid = threadIdx.x, wid = tid >> 5, lane = tid & 31;
    const int mg = blockIdx.x >> 3;
    const int j = (int)cluster_rank();
    const int wm = wid >> 2, wn = wid & 3;    // warp tile: rows wm*32, cols wn*32

    if (tid == 0) {   // two ping-pong barriers: step t uses mbar[t&1]
        asm volatile("mbarrier.init.shared.b64 [%0], %1;" :: "r"(sb + SM_MBAR), "r"(8u) : "memory");
        asm volatile("mbarrier.init.shared.b64 [%0], %1;" :: "r"(sb + SM_MBAR + 16), "r"(8u) : "memory");
    }
    if (tid < 32)
        reinterpret_cast<float4*>(smem + SM_BIAS)[tid] = reinterpret_cast<const float4*>(g_bias[j])[tid];
    {   // load W_ih image (used only at t=0)
        const unsigned char* src = g_Wimg[0][j];
        #pragma unroll
        for (int i = 0; i < 8; i++) { int q = tid + NTHR * i; cp16(sb + SM_W + q * 16, src + q * 16); }
        cp_commit();
    }
    cp_wait0();
    __syncthreads();
    cluster_sync();   // mbarrier init visible cluster-wide before any remote arrive

    // ldmatrix per-lane address bases
    const int a_row_off = (lane & 7) + (((lane >> 3) & 1) << 3);
    const int a_ch_off  = (lane >> 4) & 1;
    uint32_t a_base[2]; int a_rsw[2];
    #pragma unroll
    for (int mt = 0; mt < 2; mt++) {
        int row = wm * 32 + mt * 16 + a_row_off;
        a_base[mt] = sb + SM_A + row * 512;
        a_rsw[mt] = row & 7;
    }
    const int b_ch_off = (lane >> 3) & 1;
    uint32_t b_base[2]; int b_rsw[2];
    #pragma unroll
    for (int np = 0; np < 2; np++) {
        int nrow = wn * 32 + np * 16 + (lane & 7) + (((lane >> 4) & 1) << 3);
        b_base[np] = sb + SM_W + nrow * 512;
        b_rsw[np] = nrow & 7;
    }

    // A-tile cp.async per-thread bases: 512 threads, 4 chunks (16B) per K-half each
    const int am = tid >> 2, acb = tid & 3, amsw = am & 7;
    const uint32_t sA_row = sb + SM_A + (uint32_t)(am * 512);
    const uint32_t gA_row = (uint32_t)(am * Hd);

    // epilogue geometry: thread owns rows r0, r0+8 (x2 mt), units (2wn+up)*4 + (lane&3)
    const int r_lane = lane >> 2, u_lane = lane & 3;
    const size_t idxbase = (size_t)(mg * MT + wm * 32 + r_lane) * Hd + j * 32;
    float* const hfp = out + (size_t)Td * Bd * Hd + idxbase;   // hf, then cf at +Bd*Hd

    float cst[8], hvr[8];
    #pragma unroll
    for (int i = 0; i < 8; i++) cst[i] = 0.f;

    #pragma unroll 1
    for (int t = 0; t < Td; t++) {
        const int cur = t & 1;
        // ---- load h tile [128,256] f16 into swizzled A, two K-half groups ----
        const __half* hsrc = g_hbuf[cur] + (size_t)mg * MT * Hd;
        #pragma unroll
        for (int i = 0; i < 4; i++) {
            int ch = acb + i * 4;                         // chunk 0..15 (K-half 0)
            cp16(sA_row + (uint32_t)((ch ^ amsw) << 4), hsrc + gA_row + ch * 8);
        }
        cp_commit();
        #pragma unroll
        for (int i = 0; i < 4; i++) {
            int ch = 16 + acb + i * 4;                    // chunk 16..31 (K-half 1)
            cp16(sA_row + (uint32_t)((ch ^ amsw) << 4), hsrc + gA_row + ch * 8);
        }
        cp_commit();

        cp_wait1();          // K-half 0 ready (also drains W-swap group from t==0)
        __syncthreads();

        float acc[32];
        #pragma unroll
        for (int i = 0; i < 32; i++) acc[i] = 0.f;

        // ---- MMA K-half 0 (kt 0..7) while K-half 1 streams in ----
        #pragma unroll
        for (int kt = 0; kt < 8; kt++) {
            uint32_t af[2][4];
            #pragma unroll
            for (int mt = 0; mt < 2; mt++)
                ldsm4(af[mt], a_base[mt] + (((2 * kt + a_ch_off) ^ a_rsw[mt]) << 4));
            uint32_t bf[2][4];
            #pragma unroll
            for (int np = 0; np < 2; np++)
                ldsm4(bf[np], b_base[np] + (((2 * kt + b_ch_off) ^ b_rsw[np]) << 4));
            #pragma unroll
            for (int mt = 0; mt < 2; mt++)
                #pragma unroll
                for (int nt = 0; nt < 4; nt++)
                    mma16816(&acc[(mt * 4 + nt) * 4], af[mt], bf[nt >> 1][(nt & 1) * 2], bf[nt >> 1][(nt & 1) * 2 + 1]);
        }

        cp_wait0();          // K-half 1 ready
        __syncthreads();

        #pragma unroll
        for (int kt = 8; kt < 16; kt++) {
            uint32_t af[2][4];
            #pragma unroll
            for (int mt = 0; mt < 2; mt++)
                ldsm4(af[mt], a_base[mt] + (((2 * kt + a_ch_off) ^ a_rsw[mt]) << 4));
            uint32_t bf[2][4];
            #pragma unroll
            for (int np = 0; np < 2; np++)
                ldsm4(bf[np], b_base[np] + (((2 * kt + b_ch_off) ^ b_rsw[np]) << 4));
            #pragma unroll
            for (int mt = 0; mt < 2; mt++)
                #pragma unroll
                for (int nt = 0; nt < 4; nt++)
                    mma16816(&acc[(mt * 4 + nt) * 4], af[mt], bf[nt >> 1][(nt & 1) * 2], bf[nt >> 1][(nt & 1) * 2 + 1]);
        }

        if (t == 0) {   // all warps done reading W_ih -> swap in W_ih+W_hh
            __syncthreads();
            const unsigned char* src = g_Wimg[1][j];
            #pragma unroll
            for (int i = 0; i < 8; i++) { int q = tid + NTHR * i; cp16(sb + SM_W + q * 16, src + q * 16); }
            cp_commit();   // drained by next step's cp_wait1 before its MMA
        }

        // ---- epilogue: all 4 gates per thread (no shuffles), activations, h stores ----
        __half* hp = &g_hbuf[cur ^ 1][idxbase];
        const float4* bias4 = reinterpret_cast<const float4*>(smem + SM_BIAS);
        #pragma unroll
        for (int mt = 0; mt < 2; mt++) {
            #pragma unroll
            for (int up = 0; up < 2; up++) {
                const float* aI = &acc[(mt * 4 + 2 * up) * 4];       // (i,f) rows r0, r0+8
                const float* aG = &acc[(mt * 4 + 2 * up + 1) * 4];   // (g,o) rows r0, r0+8
                const int unit = (2 * wn + up) * 4 + u_lane;
                float4 bb = bias4[unit];
                #pragma unroll
                for (int rh = 0; rh < 2; rh++) {
                    float iv = fsig(aI[2 * rh + 0] + bb.x);
                    float fv = fsig(aI[2 * rh + 1] + bb.y);
                    float gv = ftanh(aG[2 * rh + 0] + bb.z);
                    float ov = fsig(aG[2 * rh + 1] + bb.w);
                    const int li = mt * 4 + up * 2 + rh;
                    float cn = fmaf(fv, cst[li], iv * gv);
                    cst[li] = cn;
                    float hv = ov * ftanh(cn);
                    hvr[li] = hv;
                    hp[(size_t)(mt * 16 + rh * 8) * Hd + unit] = __float2half_rn(hv);
                }
            }
        }
        __syncthreads();   // all h stores of this CTA issued & ordered before release

        // ---- release: 8 threads each arrive on one cluster peer's step-parity barrier ----
        if (tid < NSLC) mbar_arrive_remote(sb + SM_MBAR + 16 * (t & 1), (uint32_t)tid);

        // ---- deferred x_hat (and final hf/cf) stores: off the critical path ----
        const int oidx = (t == 0) ? 0 : (Td - t);   // x_hat[0]=h0, x_hat[k]=h_{T-k}
        float* xp = out + (size_t)oidx * (Bd * Hd) + idxbase;
        #pragma unroll
        for (int mt = 0; mt < 2; mt++)
            #pragma unroll
            for (int up = 0; up < 2; up++) {
                const int unit = (2 * wn + up) * 4 + u_lane;
                #pragma unroll
                for (int rh = 0; rh < 2; rh++) {
                    const int li = mt * 4 + up * 2 + rh;
                    xp[(size_t)(mt * 16 + rh * 8) * Hd + unit] = hvr[li];
                }
            }
        if (t == Td - 1) {
            #pragma unroll
            for (int mt = 0; mt < 2; mt++)
                #pragma unroll
                for (int up = 0; up < 2; up++) {
                    const int unit = (2 * wn + up) * 4 + u_lane;
                    #pragma unroll
                    for (int rh = 0; rh < 2; rh++) {
                        const int li = mt * 4 + up * 2 + rh;
                        const size_t off = (size_t)(mt * 16 + rh * 8) * Hd + unit;
                        hfp[off] = hvr[li];
                        hfp[(size_t)Bd * Hd + off] = cst[li];
                    }
                }
        }

        // ---- wait: leader observes all 8 peers, bar.sync broadcasts visibility ----
        if (tid == 0) mbar_wait_cl(sb + SM_MBAR + 16 * (t & 1), (uint32_t)((t >> 1) & 1));
        __syncthreads();
    }
    cluster_sync();
}

// ---------------- launch ----------------
extern "C" void kernel_launch(void* const* d_in, const int* in_sizes, int n_in,
                              void* d_out, int out_size) {
    const float* x   = (const float*)d_in[0];
    const float* Wih = (const float*)d_in[1];
    const float* Whh = (const float*)d_in[2];
    const float* bih = (const float*)d_in[3];
    const float* bhh = (const float*)d_in[4];
    float* out = (float*)d_out;
    (void)in_sizes; (void)n_in; (void)out_size;

    cudaFuncSetAttribute(lstm_kernel, cudaFuncAttributeMaxDynamicSharedMemorySize, SM_TOTAL);

    prep_kernel<<<2048, 256>>>(x, Wih, Whh, bih, bhh);
    lstm_kernel<<<GRID, NTHR, SM_TOTAL>>>(out);
}

// round 9
// speedup vs baseline: 1.2638x; 1.2638x over previous
#include <cuda_runtime.h>
#include <cuda_fp16.h>
#include <cstdint>

#define DINLINE __device__ __forceinline__

static constexpr int Bd = 2048;
static constexpr int Hd = 256;
static constexpr int Td = 512;
static constexpr int MT = 64;                  // batch tile rows (per tile)
static constexpr int NT = 128;                 // gate-column tile
static constexpr int NGRP = Bd / MT;           // 32 M-groups (barrier groups)
static constexpr int NSLC = (4 * Hd) / NT;     // 8 N-slices
static constexpr int GRID = 128;               // each CTA owns 2 M-tiles x 1 slice
static constexpr int NTHR = 256;               // 8 warps: 2 (M) x 4 (N), 32x32 warp tiles

// SMEM layout (dynamic)
static constexpr int SM_BIAS = 0;              // 128 floats (float4 per hidden unit: i,f,g,o)
static constexpr int SM_A0 = 1024;             // h tile0 [64][256] f16 swizzled (32KB)
static constexpr int SM_A1 = SM_A0 + 32768;    // h tile1 (32KB)
static constexpr int SM_W = SM_A0 + 65536;     // W tile [128 n][256 k] f16 swizzled (64KB)
static constexpr int SM_TOTAL = SM_W + 65536;  // 132096 B

// ---------------- device globals (scratch; no allocations) ----------------
__device__ __align__(16) __half g_hbuf[2][Bd * Hd];                  // ping-pong h (fp16)
__device__ __align__(1024) unsigned char g_Wimg[2][NSLC][65536];     // [W_ih, W_ih+W_hh] smem images
__device__ float g_bias[NSLC][NT];
__device__ unsigned int g_cnt[NGRP];
__device__ int g_gen[NGRP];

// ---------------- helpers ----------------
DINLINE uint32_t smem_u32(const void* p) {
    uint32_t a;
    asm("{ .reg .u64 t; cvta.to.shared.u64 t, %1; cvt.u32.u64 %0, t; }" : "=r"(a) : "l"(p));
    return a;
}
DINLINE void cp16(uint32_t s, const void* g) {
    asm volatile("cp.async.cg.shared.global [%0], [%1], 16;" :: "r"(s), "l"(g));
}
DINLINE void cp_commit() { asm volatile("cp.async.commit_group;" ::: "memory"); }
DINLINE void cp_wait0()  { asm volatile("cp.async.wait_group 0;" ::: "memory"); }
DINLINE void cp_wait1()  { asm volatile("cp.async.wait_group 1;" ::: "memory"); }

DINLINE void ldsm4(uint32_t* r, uint32_t addr) {
    asm volatile("ldmatrix.sync.aligned.m8n8.x4.shared.b16 {%0,%1,%2,%3}, [%4];"
                 : "=r"(r[0]), "=r"(r[1]), "=r"(r[2]), "=r"(r[3]) : "r"(addr));
}
DINLINE void mma16816(float* c, const uint32_t* a, uint32_t b0, uint32_t b1) {
    asm volatile(
        "mma.sync.aligned.m16n8k16.row.col.f32.f16.f16.f32 "
        "{%0,%1,%2,%3},{%4,%5,%6,%7},{%8,%9},{%0,%1,%2,%3};"
        : "+f"(c[0]), "+f"(c[1]), "+f"(c[2]), "+f"(c[3])
        : "r"(a[0]), "r"(a[1]), "r"(a[2]), "r"(a[3]), "r"(b0), "r"(b1));
}

// sigmoid via single-MUFU tanh.approx; tanh (feeds h directly) stays EX2+RCP precise
DINLINE float fsig(float x) {
    float t;
    asm("tanh.approx.f32 %0, %1;" : "=f"(t) : "f"(0.5f * x));
    return fmaf(0.5f, t, 0.5f);
}
DINLINE float ftanh(float x) {
    float e, r;
    asm("ex2.approx.f32 %0, %1;" : "=f"(e) : "f"(2.8853900817779268f * x));
    asm("rcp.approx.f32 %0, %1;" : "=f"(r) : "f"(1.0f + e));
    return fmaf(-2.0f, r, 1.0f);
}

// group barrier (R2-proven): last of 8 arrivals publishes generation t+1
DINLINE void grp_release(int mg, int t) {
    unsigned old;
    asm volatile("atom.acq_rel.gpu.global.add.u32 %0, [%1], %2;"
                 : "=r"(old) : "l"(&g_cnt[mg]), "r"(1u) : "memory");
    if (old == (unsigned)(8 * (t + 1) - 1)) {
        asm volatile("st.release.gpu.global.b32 [%0], %1;" :: "l"(&g_gen[mg]), "r"(t + 1) : "memory");
    }
}
DINLINE void grp_wait(int mg, int target) {
    int v;
    do {
        asm volatile("ld.acquire.gpu.global.b32 %0, [%1];" : "=r"(v) : "l"(&g_gen[mg]) : "memory");
        if (v < target) __nanosleep(32);
    } while (v < target);
}

// ---------------- prologue: permuted/swizzled fp16 W images, bias, x->fp16 ----------------
// Column permutation within a 128-col slice: 16-col groups; w=n&15:
//   w<8:  gates (i,f)  unit = 4*(n>>4) + (w>>1), gate = w&1
//   w>=8: gates (g,o)  unit = 4*(n>>4) + ((w-8)>>1), gate = 2 + (w&1)
// -> MMA thread owning cols {2c,2c+1} of n8-tiles (2p, 2p+1) gets all 4 gates of one unit.
__global__ void prep_kernel(const float* __restrict__ x,
                            const float* __restrict__ Wih, const float* __restrict__ Whh,
                            const float* __restrict__ bih, const float* __restrict__ bhh) {
    int g = blockIdx.x * blockDim.x + threadIdx.x;
    if (g < Bd * Hd) g_hbuf[0][g] = __float2half_rn(x[g]);
    if (g < 2 * NSLC * NT * Hd) {  // 524288 entries
        int set = g >> 18;
        int r = g & 262143;
        int j = r >> 15;
        int n = (r >> 8) & 127;
        int k = r & 255;
        int w = n & 15;
        int gate = 2 * (w >> 3) + (w & 1);
        int hl = (n >> 4) * 4 + ((w >> 1) & 3);
        int row = gate * Hd + j * 32 + hl;            // original W row in (4H,H)
        float wv = Wih[row * Hd + k];
        if (set) wv += Whh[row * Hd + k];
        uint32_t byte = (uint32_t)(n * 512 + (((k >> 3) ^ (n & 7)) << 4) + (k & 7) * 2);
        *reinterpret_cast<__half*>(&g_Wimg[set][j][byte]) = __float2half_rn(wv);
    }
    if (g < NSLC * NT) {           // bias as float4 (i,f,g,o) per unit: n = unit*4+gate
        int j = g >> 7, n = g & 127;
        int gate = n & 3, hl = n >> 2;
        int row = gate * Hd + j * 32 + hl;
        g_bias[j][n] = bih[row] + bhh[row];
    }
    if (g < NGRP) { g_cnt[g] = 0; g_gen[g] = 0; }
}

// full-K MMA over one 64x256 A tile vs persistent W -> acc[32] (2 mt x 4 nt x 4)
DINLINE void do_mma(float* acc, uint32_t aoff,
                    const uint32_t* a_base, const int* a_rsw, int a_ch_off,
                    const uint32_t* b_base, const int* b_rsw, int b_ch_off) {
    #pragma unroll
    for (int kt = 0; kt < 16; kt++) {
        uint32_t af[2][4];
        #pragma unroll
        for (int mt = 0; mt < 2; mt++)
            ldsm4(af[mt], a_base[mt] + aoff + (((2 * kt + a_ch_off) ^ a_rsw[mt]) << 4));
        uint32_t bf[2][4];
        #pragma unroll
        for (int np = 0; np < 2; np++)
            ldsm4(bf[np], b_base[np] + (((2 * kt + b_ch_off) ^ b_rsw[np]) << 4));
        #pragma unroll
        for (int mt = 0; mt < 2; mt++)
            #pragma unroll
            for (int nt = 0; nt < 4; nt++)
                mma16816(&acc[(mt * 4 + nt) * 4], af[mt], bf[nt >> 1][(nt & 1) * 2], bf[nt >> 1][(nt & 1) * 2 + 1]);
    }
}

// ---------------- main persistent kernel ----------------
__global__ void __launch_bounds__(NTHR, 1) lstm_kernel(float* __restrict__ out) {
    extern __shared__ __align__(1024) char smem[];
    const uint32_t sb = smem_u32(smem);
    const int tid = threadIdx.x, wid = tid >> 5, lane = tid & 31;
    const int sj = blockIdx.x & 7, cm = blockIdx.x >> 3;
    const int mg0 = cm * 2, mg1 = cm * 2 + 1;
    const int wm = wid >> 2, wn = wid & 3;    // warp tile: rows wm*32, cols wn*32

    if (tid < 32)
        reinterpret_cast<float4*>(smem + SM_BIAS)[tid] = reinterpret_cast<const float4*>(g_bias[sj])[tid];
    {   // group W: load W_ih image (used only at t=0)
        const unsigned char* src = g_Wimg[0][sj];
        #pragma unroll
        for (int i = 0; i < 16; i++) { int q = tid + NTHR * i; cp16(sb + SM_W + q * 16, src + q * 16); }
        cp_commit();
    }

    // A-tile cp.async mapping: 256 threads, row=tid>>2 (0..63), 8 chunks each
    const int am = tid >> 2, acb = tid & 3, amsw = am & 7;
    const uint32_t sA_row = (uint32_t)(am * 512);
    const uint32_t gA_row = (uint32_t)(am * Hd);
    {   // groups A0, A1: initial h tiles from g_hbuf[0]
        const __half* h0 = g_hbuf[0] + (size_t)mg0 * MT * Hd;
        #pragma unroll
        for (int i = 0; i < 8; i++) { int ch = acb + 4 * i; cp16(sb + SM_A0 + sA_row + (uint32_t)((ch ^ amsw) << 4), h0 + gA_row + ch * 8); }
        cp_commit();
        const __half* h1 = g_hbuf[0] + (size_t)mg1 * MT * Hd;
        #pragma unroll
        for (int i = 0; i < 8; i++) { int ch = acb + 4 * i; cp16(sb + SM_A1 + sA_row + (uint32_t)((ch ^ amsw) << 4), h1 + gA_row + ch * 8); }
        cp_commit();
    }

    // ldmatrix per-lane address bases (tile0; tile1 = +32768)
    const int a_row_off = (lane & 7) + (((lane >> 3) & 1) << 3);
    const int a_ch_off  = (lane >> 4) & 1;
    uint32_t a_base[2]; int a_rsw[2];
    #pragma unroll
    for (int mt = 0; mt < 2; mt++) {
        int row = wm * 32 + mt * 16 + a_row_off;
        a_base[mt] = sb + SM_A0 + row * 512;
        a_rsw[mt] = row & 7;
    }
    const int b_ch_off = (lane >> 3) & 1;
    uint32_t b_base[2]; int b_rsw[2];
    #pragma unroll
    for (int np = 0; np < 2; np++) {
        int nrow = wn * 32 + np * 16 + (lane & 7) + (((lane >> 4) & 1) << 3);
        b_base[np] = sb + SM_W + nrow * 512;
        b_rsw[np] = nrow & 7;
    }

    // epilogue geometry: thread owns rows r0,r0+8 (x2 mt), units (2wn+up)*4 + (lane&3)
    const int r_lane = lane >> 2, u_lane = lane & 3;
    size_t idxb[2];
    #pragma unroll
    for (int tau = 0; tau < 2; tau++)
        idxb[tau] = (size_t)((cm * 2 + tau) * MT + wm * 32 + r_lane) * Hd + sj * 32;

    float cst[2][8], hvr[2][8];
    #pragma unroll
    for (int tau = 0; tau < 2; tau++)
        #pragma unroll
        for (int i = 0; i < 8; i++) cst[tau][i] = 0.f;

    const float4* bias4 = reinterpret_cast<const float4*>(smem + SM_BIAS);

    #pragma unroll 1
    for (int t = 0; t < Td; t++) {
        const int cur = t & 1;
        const int oidx = (t == 0) ? 0 : (Td - t);   // x_hat[0]=h0, x_hat[k]=h_{T-k}

        #pragma unroll 1
        for (int tau = 0; tau < 2; tau++) {
            // ---- wait A tile ready, then MMA full-K ----
            if (tau == 0) cp_wait1(); else cp_wait0();
            __syncthreads();
            float acc[32];
            #pragma unroll
            for (int i = 0; i < 32; i++) acc[i] = 0.f;
            do_mma(acc, (uint32_t)(tau * 32768), a_base, a_rsw, a_ch_off, b_base, b_rsw, b_ch_off);

            // ---- epilogue: all 4 gates per thread, activations, h stores ----
            __half* hp = &g_hbuf[cur ^ 1][idxb[tau]];
            #pragma unroll
            for (int mt = 0; mt < 2; mt++) {
                #pragma unroll
                for (int up = 0; up < 2; up++) {
                    const float* aI = &acc[(mt * 4 + 2 * up) * 4];       // (i,f) rows r0, r0+8
                    const float* aG = &acc[(mt * 4 + 2 * up + 1) * 4];   // (g,o) rows r0, r0+8
                    const int unit = (2 * wn + up) * 4 + u_lane;
                    float4 bb = bias4[unit];
                    #pragma unroll
                    for (int rh = 0; rh < 2; rh++) {
                        float iv = fsig(aI[2 * rh + 0] + bb.x);
                        float fv = fsig(aI[2 * rh + 1] + bb.y);
                        float gv = ftanh(aG[2 * rh + 0] + bb.z);
                        float ov = fsig(aG[2 * rh + 1] + bb.w);
                        const int li = mt * 4 + up * 2 + rh;
                        float cn = fmaf(fv, cst[tau][li], iv * gv);
                        cst[tau][li] = cn;
                        float hv = ov * ftanh(cn);
                        hvr[tau][li] = hv;
                        hp[(size_t)(mt * 16 + rh * 8) * Hd + unit] = __float2half_rn(hv);
                    }
                }
            }
            __syncthreads();   // all h stores of this CTA issued & ordered before release
            if (tid == 0) grp_release(tau == 0 ? mg0 : mg1, t);

            // W-swap after tile1's MMA at t==0 (own cp.async group, drains by next cp_wait1)
            if (t == 0 && tau == 1) {
                const unsigned char* src = g_Wimg[1][sj];
                #pragma unroll
                for (int i = 0; i < 16; i++) { int q = tid + NTHR * i; cp16(sb + SM_W + q * 16, src + q * 16); }
                cp_commit();
            }

            // ---- deferred x_hat (and final hf/cf) stores: off the critical path ----
            float* xp = out + (size_t)oidx * (Bd * Hd) + idxb[tau];
            #pragma unroll
            for (int mt = 0; mt < 2; mt++)
                #pragma unroll
                for (int up = 0; up < 2; up++) {
                    const int unit = (2 * wn + up) * 4 + u_lane;
                    #pragma unroll
                    for (int rh = 0; rh < 2; rh++)
                        xp[(size_t)(mt * 16 + rh * 8) * Hd + unit] = hvr[tau][mt * 4 + up * 2 + rh];
                }
            if (t == Td - 1) {
                float* hfp = out + (size_t)Td * Bd * Hd + idxb[tau];
                #pragma unroll
                for (int mt = 0; mt < 2; mt++)
                    #pragma unroll
                    for (int up = 0; up < 2; up++) {
                        const int unit = (2 * wn + up) * 4 + u_lane;
                        #pragma unroll
                        for (int rh = 0; rh < 2; rh++) {
                            const int li = mt * 4 + up * 2 + rh;
                            const size_t off = (size_t)(mt * 16 + rh * 8) * Hd + unit;
                            hfp[off] = hvr[tau][li];
                            hfp[(size_t)Bd * Hd + off] = cst[tau][li];
                        }
                    }
            }
        }

        // ---- tail: wait peers per tile, then issue next-step A loads ----
        if (t < Td - 1) {
            const __half* hn = g_hbuf[cur ^ 1];
            if (tid == 0) grp_wait(mg0, t + 1);
            __syncthreads();
            {
                const __half* h0 = hn + (size_t)mg0 * MT * Hd;
                #pragma unroll
                for (int i = 0; i < 8; i++) { int ch = acb + 4 * i; cp16(sb + SM_A0 + sA_row + (uint32_t)((ch ^ amsw) << 4), h0 + gA_row + ch * 8); }
                cp_commit();
            }
            if (tid == 0) grp_wait(mg1, t + 1);
            __syncthreads();
            {
                const __half* h1 = hn + (size_t)mg1 * MT * Hd;
                #pragma unroll
                for (int i = 0; i < 8; i++) { int ch = acb + 4 * i; cp16(sb + SM_A1 + sA_row + (uint32_t)((ch ^ amsw) << 4), h1 + gA_row + ch * 8); }
                cp_commit();
            }
        }
    }
}

// ---------------- launch ----------------
extern "C" void kernel_launch(void* const* d_in, const int* in_sizes, int n_in,
                              void* d_out, int out_size) {
    const float* x   = (const float*)d_in[0];
    const float* Wih = (const float*)d_in[1];
    const float* Whh = (const float*)d_in[2];
    const float* bih = (const float*)d_in[3];
    const float* bhh = (const float*)d_in[4];
    float* out = (float*)d_out;
    (void)in_sizes; (void)n_in; (void)out_size;

    cudaFuncSetAttribute(lstm_kernel, cudaFuncAttributeMaxDynamicSharedMemorySize, SM_TOTAL);

    prep_kernel<<<2048, 256>>>(x, Wih, Whh, bih, bhh);
    lstm_kernel<<<GRID, NTHR, SM_TOTAL>>>(out);
}